// round 16
// baseline (speedup 1.0000x reference)
#include <cuda_runtime.h>
#include <cuda_bf16.h>
#include <math.h>
#include <stdint.h>

#define D 300
#define D2 600
#define LAYERS 5
#define MAXN 200000
#define MAXE 400000
#define MAXG 1024
#define BN_EPS 1e-5f

// ---- GEMM tiling ----
#define BM 64
#define BK 32
#define LDK 40            // halfwords per smem row (80B): conflict-free ldmatrix, 16B aligned
#define K1P 320           // GEMM1 K=300 padded (storage stride AND compute K)
#define K2P 640           // t row storage stride
#define K2C 608           // GEMM2 compute K (19 x 32; [600,608) zero pad)
#define N1P 640           // GEMM1 NC=600 padded (10 col tiles of 64)
#define N2P 320           // GEMM2 NC=300 padded (5 col tiles of 64)
#define ROWPAD 64
#define NSTAGES 4
#define STG_A   (BM * LDK * 2)            // 5120 B per A half

// ---------------- scratch (static device globals, zero-init .bss) ----------------
__device__ float g_h[(size_t)(MAXN + ROWPAD) * D];
__device__ float g_gsum[(size_t)MAXG * D];
__device__ float g_cnt[MAXG];
__device__ int g_deg[MAXN + 1];      // zeroed by scan after reading (invariant)
__device__ int g_rowptr[MAXN + 1];
__device__ int g_pos[MAXN];
__device__ uint32_t g_eidx[MAXE];
__device__ __nv_bfloat16 g_ah[(size_t)(MAXN + ROWPAD) * K1P];
__device__ __nv_bfloat16 g_al[(size_t)(MAXN + ROWPAD) * K1P];
__device__ __nv_bfloat16 g_th[(size_t)(MAXN + ROWPAD) * K2P];
__device__ __nv_bfloat16 g_tl[(size_t)(MAXN + ROWPAD) * K2P];
__device__ __nv_bfloat16 g_w1h[(size_t)LAYERS * N1P * K1P];
__device__ __nv_bfloat16 g_w1l[(size_t)LAYERS * N1P * K1P];
__device__ __nv_bfloat16 g_w2h[(size_t)LAYERS * N2P * K2P];
__device__ __nv_bfloat16 g_w2l[(size_t)LAYERS * N2P * K2P];

// ---------------- helpers ----------------
__device__ __forceinline__ uint32_t smem_u32(const void* p) {
    uint32_t a;
    asm("{ .reg .u64 t; cvta.to.shared.u64 t, %1; cvt.u32.u64 %0, t; }" : "=r"(a) : "l"(p));
    return a;
}
__device__ __forceinline__ void cp16(uint32_t dst, const void* src) {
    asm volatile("cp.async.cg.shared.global [%0], [%1], 16;" :: "r"(dst), "l"(src));
}
#define CP_COMMIT() asm volatile("cp.async.commit_group;" ::: "memory")
#define CP_WAIT1()  asm volatile("cp.async.wait_group 1;" ::: "memory")
__device__ __forceinline__ void ldsm_x4(uint32_t* r, uint32_t addr) {
    asm volatile("ldmatrix.sync.aligned.m8n8.x4.shared.b16 {%0,%1,%2,%3}, [%4];"
                 : "=r"(r[0]), "=r"(r[1]), "=r"(r[2]), "=r"(r[3]) : "r"(addr));
}
__device__ __forceinline__ void ldsm_x2(uint32_t* r, uint32_t addr) {
    asm volatile("ldmatrix.sync.aligned.m8n8.x2.shared.b16 {%0,%1}, [%2];"
                 : "=r"(r[0]), "=r"(r[1]) : "r"(addr));
}
__device__ __forceinline__ void mma_bf16(float* c, const uint32_t* a, const uint32_t* b) {
    asm volatile("mma.sync.aligned.m16n8k16.row.col.f32.bf16.bf16.f32 "
                 "{%0,%1,%2,%3}, {%4,%5,%6,%7}, {%8,%9}, {%0,%1,%2,%3};"
                 : "+f"(c[0]), "+f"(c[1]), "+f"(c[2]), "+f"(c[3])
                 : "r"(a[0]), "r"(a[1]), "r"(a[2]), "r"(a[3]), "r"(b[0]), "r"(b[1]));
}
__device__ __forceinline__ uint32_t pack2(float x0, float x1, float& r0, float& r1) {
    __nv_bfloat16 h0 = __float2bfloat16_rn(x0);
    __nv_bfloat16 h1 = __float2bfloat16_rn(x1);
    r0 = x0 - __bfloat162float(h0);
    r1 = x1 - __bfloat162float(h1);
    return ((uint32_t)__bfloat16_as_ushort(h1) << 16) | (uint32_t)__bfloat16_as_ushort(h0);
}
__device__ __forceinline__ uint32_t pack2lo(float r0, float r1) {
    __nv_bfloat16 l0 = __float2bfloat16_rn(r0);
    __nv_bfloat16 l1 = __float2bfloat16_rn(r1);
    return ((uint32_t)__bfloat16_as_ushort(l1) << 16) | (uint32_t)__bfloat16_as_ushort(l0);
}

// -------- launch 1: mega init (hist atomics + node emb + weight split) --------
// deg is pre-zeroed: .bss on first call, re-zeroed by scan_kernel on every call.
__global__ void mega_init_kernel(const int* __restrict__ an, const int* __restrict__ ct,
                                 const int* __restrict__ dst,
                                 const float* __restrict__ ne0, const float* __restrict__ ne1,
                                 const float* __restrict__ W1, const float* __restrict__ W2,
                                 float* __restrict__ h, int* __restrict__ deg,
                                 __nv_bfloat16* __restrict__ w1h, __nv_bfloat16* __restrict__ w1l,
                                 __nv_bfloat16* __restrict__ w2h, __nv_bfloat16* __restrict__ w2l,
                                 int N, int E) {
    const int BH = (MAXE + 255) / 256;
    const long NH = (long)MAXN * D;
    const int B1 = (int)((NH + 255) / 256);
    const int B2 = LAYERS * N1P * K1P / 256;
    int b = blockIdx.x;
    if (b < BH) {
        int e = b * 256 + threadIdx.x;
        if (e < E) atomicAdd(&deg[dst[e] + 1], 1);
    } else if (b < BH + B1) {
        long idx = (long)(b - BH) * 256 + threadIdx.x;
        if (idx < (long)N * D) {
            int i = (int)(idx / D), d = (int)(idx - (long)i * D);
            h[idx] = ne0[(size_t)an[i] * D + d] + ne1[(size_t)ct[i] * D + d];
        }
    } else if (b < BH + B1 + B2) {
        int idx = (b - BH - B1) * 256 + threadIdx.x;
        int l = idx / (N1P * K1P);
        int lk = idx - l * (N1P * K1P);
        int n = lk / K1P, k = lk - n * K1P;
        float x = (n < D2 && k < D) ? W1[(size_t)l * D * D2 + (size_t)k * D2 + n] : 0.0f;
        __nv_bfloat16 hi = __float2bfloat16_rn(x);
        w1h[idx] = hi;
        w1l[idx] = __float2bfloat16_rn(x - __bfloat162float(hi));
    } else {
        int idx = (b - BH - B1 - B2) * 256 + threadIdx.x;
        int l = idx / (N2P * K2P);
        int lk = idx - l * (N2P * K2P);
        int n = lk / K2P, k = lk - n * K2P;
        float x = (n < D && k < D2) ? W2[(size_t)l * D2 * D + (size_t)k * D + n] : 0.0f;
        __nv_bfloat16 hi = __float2bfloat16_rn(x);
        w2h[idx] = hi;
        w2l[idx] = __float2bfloat16_rn(x - __bfloat162float(hi));
    }
}

// -------- launch 2: single-block inclusive scan; reads deg, zeroes it for next call --------
__global__ void scan_kernel(int* __restrict__ deg, int* __restrict__ rowptr,
                            int* __restrict__ pos, int N) {
    __shared__ int ss[1024];
    int t = threadIdx.x;
    int n = N + 1;
    int len = (n + 1023) >> 10;
    int beg = t * len, end = beg + len;
    if (end > n) end = n;
    int s = 0;
    for (int i = beg; i < end; i++) s += deg[i];
    ss[t] = s;
    __syncthreads();
    for (int off = 1; off < 1024; off <<= 1) {
        int v = (t >= off) ? ss[t - off] : 0;
        __syncthreads();
        ss[t] += v;
        __syncthreads();
    }
    int run = (t > 0) ? ss[t - 1] : 0;
    for (int i = beg; i < end; i++) {
        run += deg[i];
        deg[i] = 0;                     // restore invariant for next replay
        rowptr[i] = run;
        if (i < N) pos[i] = run;
    }
}

// -------- launch 3: scatter edges into CSR (packed src|bt|bd) --------
__global__ void scatter_kernel(const int* __restrict__ src, const int* __restrict__ dst,
                               const int* __restrict__ bt, const int* __restrict__ bd,
                               int* __restrict__ pos, uint32_t* __restrict__ eidx, int E) {
    int e = blockIdx.x * 256 + threadIdx.x;
    if (e >= E) return;
    int p = atomicAdd(&pos[dst[e]], 1);
    eidx[p] = (uint32_t)src[e] | ((uint32_t)bt[e] << 18) | ((uint32_t)bd[e] << 21);
}

// -------- per-layer: segmented message sum + split store (float2 path) --------
__global__ void aggsplit_kernel(const float* __restrict__ h,
                                const float* __restrict__ ee0, const float* __restrict__ ee1,
                                const int* __restrict__ rowptr, const uint32_t* __restrict__ eidx,
                                __nv_bfloat16* __restrict__ ah, __nv_bfloat16* __restrict__ al,
                                int N) {
    int i = blockIdx.x * 8 + (threadIdx.x >> 5);
    if (i >= N) return;
    int lane = threadIdx.x & 31;
    float2 acc[5];
#pragma unroll
    for (int j = 0; j < 5; j++) acc[j] = make_float2(0.0f, 0.0f);
    int beg = rowptr[i], end = rowptr[i + 1];
    for (int e = beg; e < end; e++) {
        uint32_t p = eidx[e];
        const float2* hs = (const float2*)(h + (size_t)(p & 0x3FFFF) * D);
        const float2* e0 = (const float2*)(ee0 + (size_t)((p >> 18) & 7) * D);
        const float2* e1 = (const float2*)(ee1 + (size_t)(p >> 21) * D);
#pragma unroll
        for (int j = 0; j < 5; j++) {
            int pr = lane + 32 * j;
            if (pr < 150) {
                float2 a = hs[pr], b = e0[pr], c = e1[pr];
                acc[j].x += a.x + b.x + c.x;
                acc[j].y += a.y + b.y + c.y;
            }
        }
    }
    size_t ro = (size_t)i * K1P;
#pragma unroll
    for (int j = 0; j < 5; j++) {
        int pr = lane + 32 * j;
        if (pr < 150) {
            float r0, r1;
            uint32_t hp = pack2(acc[j].x, acc[j].y, r0, r1);
            uint32_t lp = pack2lo(r0, r1);
            *(uint32_t*)(ah + ro + pr * 2) = hp;
            *(uint32_t*)(al + ro + pr * 2) = lp;
        }
    }
}

// ---------------- pipelined split-bf16 mma.sync GEMM ----------------
// BM=64 rows; warps 2x4; warp tile = 32 x (8*TN_T); BN_T = 32*TN_T
// 4 stages, single __syncthreads per chunk (next load hits (ch+3)%4 != ch%4)
template<int BN_T, int TN_T>
__global__ void __launch_bounds__(256, 2)
gemm_pipe_kernel(const __nv_bfloat16* __restrict__ Ah, const __nv_bfloat16* __restrict__ Al,
                 const __nv_bfloat16* __restrict__ Bh, const __nv_bfloat16* __restrict__ Bl,
                 const float* __restrict__ bias,
                 __nv_bfloat16* __restrict__ Th, __nv_bfloat16* __restrict__ Tl,
                 float* __restrict__ Cf,
                 int M, int Kp, int ldA, int ldB, int NC, int mode,
                 const float* __restrict__ bn_g, const float* __restrict__ bn_b,
                 const float* __restrict__ bn_m, const float* __restrict__ bn_v) {
    constexpr int STG_B = BN_T * LDK * 2;
    constexpr int STAGE_BYTES = 2 * STG_A + 2 * STG_B;
    constexpr int NCHUNK = 512 + BN_T * 8;          // 16B cp.async chunks per stage
    constexpr int LCH = NCHUNK / 256;
    extern __shared__ __align__(16) char dsm[];
    const uint32_t sb = smem_u32(dsm);
    const int tid = threadIdx.x;
    const int wid = tid >> 5;
    const int lane = tid & 31;
    const int warp_m = wid >> 2;
    const int warp_n = wid & 3;
    const int row_base = blockIdx.y * BM;
    const int col_base = blockIdx.x * BN_T;
    const int nch = Kp / BK;

    const uint32_t a_lane = ((uint32_t)((lane & 15) * LDK + ((lane & 16) ? 8 : 0))) * 2;
    const uint32_t b_lane = ((uint32_t)((lane & 7) * LDK + ((lane & 8) ? 8 : 0))) * 2;

    float acc[2 * TN_T][4];
#pragma unroll
    for (int i = 0; i < 2 * TN_T; i++)
#pragma unroll
        for (int j = 0; j < 4; j++) acc[i][j] = 0.0f;

    auto load_stage = [&](int stg, int k0) {
        uint32_t base = sb + stg * STAGE_BYTES;
#pragma unroll
        for (int j = 0; j < LCH; j++) {
            int id = j * 256 + tid;
            uint32_t dst;
            const __nv_bfloat16* src;
            if (id < 512) {                       // A: 64 rows x 4 chunks x 2 halves
                int half = id >> 8;
                int q = id & 255;
                int r = q >> 2, c = q & 3;
                dst = base + half * STG_A + (uint32_t)(r * 80 + c * 16);
                src = (half ? Al : Ah) + (size_t)(row_base + r) * ldA + k0 + c * 8;
            } else {                              // B: BN_T rows x 4 chunks x 2 halves
                int id2 = id - 512;
                int half = id2 / (BN_T * 4);
                int q = id2 - half * (BN_T * 4);
                int r = q >> 2, c = q & 3;
                dst = base + 2 * STG_A + half * STG_B + (uint32_t)(r * 80 + c * 16);
                src = (half ? Bl : Bh) + (size_t)(col_base + r) * ldB + k0 + c * 8;
            }
            cp16(dst, src);
        }
    };

    load_stage(0, 0);
    CP_COMMIT();
    load_stage(1, BK);
    CP_COMMIT();

    for (int ch = 0; ch < nch; ch++) {
        CP_WAIT1();
        __syncthreads();
        if (ch + 2 < nch) load_stage((ch + 2) % NSTAGES, (ch + 2) * BK);
        CP_COMMIT();

        const uint32_t ah = sb + (ch % NSTAGES) * STAGE_BYTES;
        const uint32_t al = ah + STG_A;
        const uint32_t bh = ah + 2 * STG_A;
        const uint32_t bl = bh + STG_B;
#pragma unroll
        for (int ks = 0; ks < 2; ks++) {
            uint32_t af_h[2][4], af_l[2][4], bf_h[TN_T][2], bf_l[TN_T][2];
#pragma unroll
            for (int tm = 0; tm < 2; tm++) {
                uint32_t toff = (uint32_t)(((warp_m * 32 + tm * 16) * LDK + ks * 16) * 2) + a_lane;
                ldsm_x4(af_h[tm], ah + toff);
                ldsm_x4(af_l[tm], al + toff);
            }
#pragma unroll
            for (int tn = 0; tn < TN_T; tn++) {
                uint32_t toff = (uint32_t)(((warp_n * (8 * TN_T) + tn * 8) * LDK + ks * 16) * 2) + b_lane;
                ldsm_x2(bf_h[tn], bh + toff);
                ldsm_x2(bf_l[tn], bl + toff);
            }
#pragma unroll
            for (int tm = 0; tm < 2; tm++)
#pragma unroll
                for (int tn = 0; tn < TN_T; tn++) {
                    mma_bf16(acc[tm * TN_T + tn], af_h[tm], bf_h[tn]);
                    mma_bf16(acc[tm * TN_T + tn], af_h[tm], bf_l[tn]);
                    mma_bf16(acc[tm * TN_T + tn], af_l[tm], bf_h[tn]);
                }
        }
        // no trailing barrier: with 4 stages the next load writes (ch+3)%4,
        // and the iteration that reuses ch%4 is gated by two later top-barriers
    }

    // ---- epilogue ----
    const int r_base = row_base + warp_m * 32 + (lane >> 2);
    const int c_base2 = col_base + warp_n * (8 * TN_T) + (lane & 3) * 2;
#pragma unroll
    for (int tn = 0; tn < TN_T; tn++) {
        int c = c_base2 + tn * 8;
        if (c >= NC) continue;
        float bia0 = bias[c], bia1 = bias[c + 1];
        float sc0 = 0, sc1 = 0, mn0 = 0, mn1 = 0, bb0 = 0, bb1 = 0;
        if (!Th) {
            sc0 = bn_g[c] * rsqrtf(bn_v[c] + BN_EPS);
            sc1 = bn_g[c + 1] * rsqrtf(bn_v[c + 1] + BN_EPS);
            mn0 = bn_m[c]; mn1 = bn_m[c + 1];
            bb0 = bn_b[c]; bb1 = bn_b[c + 1];
        }
#pragma unroll
        for (int tm = 0; tm < 2; tm++) {
            const float* a4 = acc[tm * TN_T + tn];
#pragma unroll
            for (int half = 0; half < 2; half++) {
                int r = r_base + tm * 16 + half * 8;
                if (r >= M) continue;
                float x0 = a4[half * 2 + 0] + bia0;
                float x1 = a4[half * 2 + 1] + bia1;
                if (Th) {
                    x0 = fmaxf(x0, 0.0f); x1 = fmaxf(x1, 0.0f);
                    float r0, r1;
                    uint32_t hp = pack2(x0, x1, r0, r1);
                    uint32_t lp = pack2lo(r0, r1);
                    size_t off = (size_t)r * K2P + c;
                    *(uint32_t*)(Th + off) = hp;
                    *(uint32_t*)(Tl + off) = lp;
                } else {
                    x0 = (x0 - mn0) * sc0 + bb0;
                    x1 = (x1 - mn1) * sc1 + bb1;
                    if (mode == 2) { x0 = fmaxf(x0, 0.0f); x1 = fmaxf(x1, 0.0f); }
                    *(float2*)(Cf + (size_t)r * NC + c) = make_float2(x0, x1);
                }
            }
        }
    }
}

// ---------------- pooling + head ----------------
__global__ void pool_kernel(const float* __restrict__ h, const int* __restrict__ gid,
                            float* __restrict__ gsum, float* __restrict__ cnt, int N) {
    int i = blockIdx.x * 8 + (threadIdx.x >> 5);
    if (i >= N) return;
    int lane = threadIdx.x & 31;
    int g = gid[i];
    const float* hr = h + (size_t)i * D;
    float* out = gsum + (size_t)g * D;
    for (int d = lane; d < D; d += 32)
        atomicAdd(&out[d], hr[d]);
    if (lane == 0)
        atomicAdd(&cnt[g], 1.0f);
}

__global__ void head_kernel(const float* __restrict__ gsum, const float* __restrict__ cnt,
                            const float* __restrict__ Wd, const float* __restrict__ bd,
                            float* __restrict__ out, int G) {
    __shared__ float row[D];
    int g = blockIdx.x;
    if (g >= G) return;
    float inv = 1.0f / fmaxf(cnt[g], 1.0f);
    for (int k = threadIdx.x; k < D; k += blockDim.x)
        row[k] = gsum[(size_t)g * D + k] * inv;
    __syncthreads();
    int c = threadIdx.x;
    float acc = bd[c];
#pragma unroll 4
    for (int k = 0; k < D; k++)
        acc = fmaf(row[k], Wd[(size_t)k * 256 + c], acc);
    out[(size_t)g * 256 + c] = acc;
}

// ---------------- launch ----------------
extern "C" void kernel_launch(void* const* d_in, const int* in_sizes, int n_in,
                              void* d_out, int out_size) {
    const int*   atomic_number = (const int*)d_in[0];
    const int*   chirality     = (const int*)d_in[1];
    const int*   bond_type     = (const int*)d_in[2];
    const int*   bond_dir      = (const int*)d_in[3];
    const int*   src           = (const int*)d_in[4];
    const int*   dst           = (const int*)d_in[5];
    const int*   gid           = (const int*)d_in[6];
    const float* ne0           = (const float*)d_in[8];
    const float* ne1           = (const float*)d_in[9];
    const float* ee0           = (const float*)d_in[10];
    const float* ee1           = (const float*)d_in[11];
    const float* W1            = (const float*)d_in[12];
    const float* b1            = (const float*)d_in[13];
    const float* W2            = (const float*)d_in[14];
    const float* b2            = (const float*)d_in[15];
    const float* gamma         = (const float*)d_in[16];
    const float* beta          = (const float*)d_in[17];
    const float* mean          = (const float*)d_in[18];
    const float* var           = (const float*)d_in[19];
    const float* Wd            = (const float*)d_in[20];
    const float* bd            = (const float*)d_in[21];
    float* out = (float*)d_out;

    int N = in_sizes[0];
    int E = in_sizes[2];
    int G = out_size / 256;
    if (N > MAXN) N = MAXN;
    if (E > MAXE) E = MAXE;
    if (G > MAXG) G = MAXG;

    constexpr int SMEM64 = NSTAGES * (2 * STG_A + 2 * 64 * LDK * 2);  // 4 * 20480 = 81920
    static int attr_set = 0;
    if (!attr_set) {
        cudaFuncSetAttribute(gemm_pipe_kernel<64, 2>, cudaFuncAttributeMaxDynamicSharedMemorySize, SMEM64);
        attr_set = 1;
    }

    float *h_ptr, *gsum_ptr, *cnt_ptr;
    int *deg, *rowptr, *pos;
    uint32_t* eidx;
    __nv_bfloat16 *ah, *al, *th, *tl, *w1h, *w1l, *w2h, *w2l;
    cudaGetSymbolAddress((void**)&h_ptr, g_h);
    cudaGetSymbolAddress((void**)&gsum_ptr, g_gsum);
    cudaGetSymbolAddress((void**)&cnt_ptr, g_cnt);
    cudaGetSymbolAddress((void**)&deg, g_deg);
    cudaGetSymbolAddress((void**)&rowptr, g_rowptr);
    cudaGetSymbolAddress((void**)&pos, g_pos);
    cudaGetSymbolAddress((void**)&eidx, g_eidx);
    cudaGetSymbolAddress((void**)&ah, g_ah);
    cudaGetSymbolAddress((void**)&al, g_al);
    cudaGetSymbolAddress((void**)&th, g_th);
    cudaGetSymbolAddress((void**)&tl, g_tl);
    cudaGetSymbolAddress((void**)&w1h, g_w1h);
    cudaGetSymbolAddress((void**)&w1l, g_w1l);
    cudaGetSymbolAddress((void**)&w2h, g_w2h);
    cudaGetSymbolAddress((void**)&w2l, g_w2l);

    // launch 1: fused init (hist + node emb + weight transpose/split)
    {
        const int BH = (MAXE + 255) / 256;
        const int B1 = (int)(((long)MAXN * D + 255) / 256);
        const int B2 = LAYERS * N1P * K1P / 256;
        const int B3 = LAYERS * N2P * K2P / 256;
        mega_init_kernel<<<BH + B1 + B2 + B3, 256>>>(
            atomic_number, chirality, dst, ne0, ne1, W1, W2,
            h_ptr, deg, w1h, w1l, w2h, w2l, N, E);
    }
    // launch 2: scan (reads deg, zeroes it, writes rowptr/pos)
    scan_kernel<<<1, 1024>>>(deg, rowptr, pos, N);
    // launch 3: scatter
    scatter_kernel<<<(E + 255) / 256, 256>>>(src, dst, bond_type, bond_dir, pos, eidx, E);

    const int nrb = (N + BM - 1) / BM;
    for (int l = 0; l < LAYERS; l++) {
        // fused message-sum + bf16 split (launch 4 on l=0 = ncu capture slot)
        aggsplit_kernel<<<(N + 7) / 8, 256>>>(h_ptr,
                                              ee0 + (size_t)l * 6 * D,
                                              ee1 + (size_t)l * 3 * D,
                                              rowptr, eidx, ah, al, N);
        // GEMM1: t = relu(agg @ W1 + b1), split-stored; BN=64 tiles
        {
            dim3 grid(N1P / 64, nrb);
            gemm_pipe_kernel<64, 2><<<grid, 256, SMEM64>>>(
                ah, al, w1h + (size_t)l * N1P * K1P, w1l + (size_t)l * N1P * K1P,
                b1 + (size_t)l * D2, th, tl, nullptr,
                N, K1P, K1P, K1P, D2, 0, nullptr, nullptr, nullptr, nullptr);
        }
        // GEMM2: h = [relu](BN(t @ W2 + b2)); compute K = 608, strides 640
        {
            dim3 grid(N2P / 64, nrb);
            int mode = (l < LAYERS - 1) ? 2 : 1;
            gemm_pipe_kernel<64, 2><<<grid, 256, SMEM64>>>(
                th, tl, w2h + (size_t)l * N2P * K2P, w2l + (size_t)l * N2P * K2P,
                b2 + (size_t)l * D, nullptr, nullptr, h_ptr,
                N, K2C, K2P, K2P, D, mode,
                gamma + (size_t)l * D, beta + (size_t)l * D,
                mean + (size_t)l * D, var + (size_t)l * D);
        }
    }

    cudaMemsetAsync(gsum_ptr, 0, (size_t)G * D * sizeof(float));
    cudaMemsetAsync(cnt_ptr, 0, (size_t)G * sizeof(float));
    pool_kernel<<<(N + 7) / 8, 256>>>(h_ptr, gid, gsum_ptr, cnt_ptr, N);
    head_kernel<<<G, 256>>>(gsum_ptr, cnt_ptr, Wd, bd, out, G);
}